// round 6
// baseline (speedup 1.0000x reference)
#include <cuda_runtime.h>
#include <cuda_bf16.h>

// FCOS loss: focal cls + centerness BCE + GIoU reg, fully fused single kernel.
// B=16, C=80, S=17064, levels hw = {12800,3200,800,208,56}.
// One thread per position; 8 blocks/SM (regs<=32) -> ~90% occupancy, 1 wave.

#define BATCH 16
#define NCLS 80
#define STOT 17064
#define NCHUNK 69                 // 50+13+4+1+1 chunks of 256 positions
#define NBLK (BATCH * NCHUNK)     // 1104 blocks, 7.46/SM, single wave at 8/SM
#define C_NM 0.5198603854199589f  // 0.75 * ln2   (non-match weight, log2 domain)
#define C_M  0.17328679513998632f // 0.25 * ln2   (match weight)
#define L2E  1.4426950408889634f
#define LN2  0.6931471805599453f

struct Ptrs {
    const float* cls[5];
    const float* cnt[5];
    const float* reg[5];
};

__device__ float g_cls[NBLK];
__device__ float g_cnt[NBLK];
__device__ float g_reg[NBLK];
__device__ float g_pos[NBLK];
__device__ int   g_sem;           // zero-init; reset by last block each call

__device__ __forceinline__ float wsum(float v) {
    #pragma unroll
    for (int o = 16; o; o >>= 1) v += __shfl_down_sync(0xffffffffu, v, o);
    return v;
}

// log2(1+e^x) * sigmoid(x)^2 accumulated into acc (caller scales by a*ln2)
__device__ __forceinline__ void focal_acc(float x, float& acc) {
    float e  = exp2f(x * L2E);        // MUFU.EX2
    float u  = 1.f + e;
    float sp = __log2f(u);            // MUFU.LG2
    float sg = __fdividef(e, u);      // MUFU.RCP + FMUL
    acc = fmaf(sp, sg * sg, acc);
}

__device__ __forceinline__ float focal_one(float x) {
    float a = 0.f; focal_acc(x, a); return a;
}

__global__ __launch_bounds__(256, 8) void k_main(
    Ptrs P,
    const float* __restrict__ cnt_t,
    const float* __restrict__ reg_t,
    const int* __restrict__ cls_t32,   // int32 view; may actually be int64 data
    float* __restrict__ out)
{
    int bid = blockIdx.x;
    int b = bid / NCHUNK;
    int chunk = bid - b * NCHUNK;

    int hw, sb, base, lvl;
    if (chunk < 50)      { hw = 12800; sb = 0;     base = chunk << 8;        lvl = 0; }
    else if (chunk < 63) { hw = 3200;  sb = 12800; base = (chunk - 50) << 8; lvl = 1; }
    else if (chunk < 67) { hw = 800;   sb = 16000; base = (chunk - 63) << 8; lvl = 2; }
    else if (chunk < 68) { hw = 208;   sb = 16800; base = 0;                 lvl = 3; }
    else                 { hw = 56;    sb = 17008; base = 0;                 lvl = 4; }

    int tid = threadIdx.x;
    int lane = tid & 31;

    // ---- dtype sniff: little-endian int64 -> odd int32 words (high words) are 0.
    int probe = cls_t32[2 * lane + 1];
    bool is64 = (__ballot_sync(0xffffffffu, probe != 0) == 0u);

    int p = base + tid;
    bool v = p < hw;
    int pc = v ? p : 0;
    size_t ti = (size_t)b * STOT + sb + pc;

    int   tgt = is64 ? __ldg(cls_t32 + 2 * ti) : __ldg(cls_t32 + ti);
    float ct  = __ldg(cnt_t + ti);

    // ---- focal cls first (minimal live regs through the hot loop) ----
    const float* cb = P.cls[lvl] + (size_t)b * NCLS * hw + pc;
    float ac0 = 0.f, ac1 = 0.f;
    float buf[8];
    #pragma unroll
    for (int g = 0; g < 10; g++) {
        const float* q = cb + (size_t)(8 * g) * hw;
        #pragma unroll
        for (int i = 0; i < 8; i++) buf[i] = __ldg(q + (size_t)i * hw);
        #pragma unroll
        for (int i = 0; i < 8; i++) focal_acc(buf[i], (i & 1) ? ac1 : ac0);
    }
    float a_cls = C_NM * (ac0 + ac1);

    // fixup for the single matched channel (tgt in 1..80)
    if ((unsigned)(tgt - 1) < NCLS) {
        float x = __ldg(cb + (size_t)(tgt - 1) * hw);
        a_cls += C_M * focal_one(-x) - C_NM * focal_one(x);
    }
    if (!v) a_cls = 0.f;

    // ---- centerness BCE + GIoU (registers reused from focal section) ----
    float a_cnt = 0.f, a_reg = 0.f, a_pos = 0.f;
    if (v && ct > -1.0f) {
        a_pos = 1.f;
        float cv = __ldg(P.cnt[lvl] + (size_t)b * hw + pc);
        {
            float e = exp2f(-fabsf(cv) * L2E);
            a_cnt = fmaxf(cv, 0.f) - cv * ct + LN2 * __log2f(1.f + e);
        }
        const float* rp = P.reg[lvl] + (size_t)b * 4 * hw + pc;
        float pl = __ldg(rp);
        float pt = __ldg(rp + (size_t)hw);
        float pr = __ldg(rp + (size_t)2 * hw);
        float pb = __ldg(rp + (size_t)3 * hw);
        float4 rt = __ldg(reinterpret_cast<const float4*>(reg_t + ti * 4));

        float wmin = fmaxf(fminf(pr, rt.z) + fminf(pl, rt.x), 0.f);
        float hmin = fmaxf(fminf(pb, rt.w) + fminf(pt, rt.y), 0.f);
        float ov   = wmin * hmin;
        float uni  = (pr + pl) * (pb + pt) + (rt.z + rt.x) * (rt.w + rt.y) - ov;
        float wmax = fmaxf(fmaxf(pr, rt.z) + fmaxf(pl, rt.x), 0.f);
        float hmax = fmaxf(fmaxf(pb, rt.w) + fmaxf(pt, rt.y), 0.f);
        float ga   = wmax * hmax;
        a_reg = 1.f - __fdividef(ov, uni) + __fdividef(ga - uni, fmaxf(ga, 1e-10f));
    }

    // ---- block reduction into per-block slots (deterministic) ----
    a_cls = wsum(a_cls); a_cnt = wsum(a_cnt); a_reg = wsum(a_reg); a_pos = wsum(a_pos);

    __shared__ float sm[8][4];
    int w = tid >> 5;
    if (lane == 0) { sm[w][0] = a_cls; sm[w][1] = a_cnt; sm[w][2] = a_reg; sm[w][3] = a_pos; }
    __syncthreads();
    if (w == 0 && lane < 8) {
        float x0 = sm[lane][0], x1 = sm[lane][1], x2 = sm[lane][2], x3 = sm[lane][3];
        #pragma unroll
        for (int o = 4; o; o >>= 1) {
            x0 += __shfl_down_sync(0xffu, x0, o);
            x1 += __shfl_down_sync(0xffu, x1, o);
            x2 += __shfl_down_sync(0xffu, x2, o);
            x3 += __shfl_down_sync(0xffu, x3, o);
        }
        if (lane == 0) {
            g_cls[bid] = x0; g_cnt[bid] = x1; g_reg[bid] = x2; g_pos[bid] = x3;
        }
    }

    // ---- last block finishes: parallel final combine ----
    __shared__ bool is_last;
    __threadfence();
    if (tid == 0) is_last = (atomicAdd(&g_sem, 1) == NBLK - 1);
    __syncthreads();
    if (!is_last) return;

    int bt = tid >> 4;       // batch 0..15
    int j  = tid & 15;
    float cls = 0.f, cnt = 0.f, reg = 0.f, pos = 0.f;
    for (int c = j; c < NCHUNK; c += 16) {
        int i = bt * NCHUNK + c;
        cls += g_cls[i]; cnt += g_cnt[i]; reg += g_reg[i]; pos += g_pos[i];
    }
    #pragma unroll
    for (int o = 8; o; o >>= 1) {
        cls += __shfl_down_sync(0xffffffffu, cls, o, 16);
        cnt += __shfl_down_sync(0xffffffffu, cnt, o, 16);
        reg += __shfl_down_sync(0xffffffffu, reg, o, 16);
        pos += __shfl_down_sync(0xffffffffu, pos, o, 16);
    }
    __shared__ float s3[16][3];
    if (j == 0) {
        float np = fmaxf(pos, 1.f);
        s3[bt][0] = cls / np; s3[bt][1] = cnt / np; s3[bt][2] = reg / np;
    }
    __syncthreads();
    if (tid < 16) {
        float c0 = s3[tid][0], c1 = s3[tid][1], c2 = s3[tid][2];
        #pragma unroll
        for (int o = 8; o; o >>= 1) {
            c0 += __shfl_down_sync(0xffffu, c0, o, 16);
            c1 += __shfl_down_sync(0xffffu, c1, o, 16);
            c2 += __shfl_down_sync(0xffffu, c2, o, 16);
        }
        if (tid == 0) {
            c0 *= (1.f / BATCH); c1 *= (1.f / BATCH); c2 *= (1.f / BATCH);
            out[0] = c0; out[1] = c1; out[2] = c2; out[3] = c0 + c1 + c2;
            g_sem = 0;   // reset for next graph replay
        }
    }
}

extern "C" void kernel_launch(void* const* d_in, const int* in_sizes, int n_in,
                              void* d_out, int out_size)
{
    // Three candidate input orderings, disambiguated by element counts:
    //  interleaved (dict):    in_sizes[1] = cnt_p0 = 204800
    //  alphabetical (names):  in_sizes[5] = cls_targets = 273024
    //  grouped (signature):   otherwise
    Ptrs P;
    const float* cnt_t;
    const float* reg_t;
    const int*   cls_t;

    if (in_sizes[1] == 204800) {                    // interleaved
        for (int i = 0; i < 5; i++) {
            P.cls[i] = (const float*)d_in[3 * i + 0];
            P.cnt[i] = (const float*)d_in[3 * i + 1];
            P.reg[i] = (const float*)d_in[3 * i + 2];
        }
        cnt_t = (const float*)d_in[15];
        reg_t = (const float*)d_in[16];
        cls_t = (const int*)d_in[17];
    } else if (in_sizes[5] == 273024) {             // alphabetical
        for (int i = 0; i < 5; i++) {
            P.cls[i] = (const float*)d_in[i];
            P.cnt[i] = (const float*)d_in[6 + i];
            P.reg[i] = (const float*)d_in[12 + i];
        }
        cls_t = (const int*)d_in[5];
        cnt_t = (const float*)d_in[11];
        reg_t = (const float*)d_in[17];
    } else {                                        // grouped (signature order)
        for (int i = 0; i < 5; i++) {
            P.cls[i] = (const float*)d_in[i];
            P.cnt[i] = (const float*)d_in[5 + i];
            P.reg[i] = (const float*)d_in[10 + i];
        }
        cnt_t = (const float*)d_in[15];
        reg_t = (const float*)d_in[16];
        cls_t = (const int*)d_in[17];
    }

    k_main<<<NBLK, 256>>>(P, cnt_t, reg_t, cls_t, (float*)d_out);
}